// round 13
// baseline (speedup 1.0000x reference)
#include <cuda_runtime.h>
#include <cuda_bf16.h>

#define HIDDEN   64
#define SEQ_LEN  128
#define BATCH    64
#define NPTS     (BATCH * SEQ_LEN)   // 8192
#define T_MAX_V  20.0f
#define KTERMS   40
#define NBLK_ROLL (BATCH / 2)        // 32 rollout blocks, 2 batches each
#define NBLK_B   256                 // reward grid
#define NTHR_B   256

// ---------------- device scratch ----------------
__device__ float  g_lc[NPTS];
__device__ int    g_nl = 0;          // reset by finalize each run (graph-safe)
__device__ float  g_llp[NBLK_B];
__device__ double g_Me[KTERMS];
__device__ double g_Ml[KTERMS];

// c_k = 2^k / k!
__constant__ double c_coef[KTERMS] = {
    1.0, 2.0, 2.0, 1.3333333333333333, 0.6666666666666666,
    0.26666666666666666, 0.08888888888888889, 0.025396825396825397,
    0.006349206349206349, 0.0014109347442680775, 2.821869488536155e-04,
    5.130671797338464e-05, 8.551119662230773e-06, 1.3155568711124266e-06,
    1.8793669587320378e-07, 2.505822611642717e-08, 3.132278264553396e-09,
    3.6850332524157603e-10, 4.0944813915730673e-11, 4.3099804121822816e-12,
    4.3099804121822815e-13, 4.104743249697411e-14, 3.7315847724521917e-15,
    3.244856323871471e-16, 2.7040469365595593e-17, 2.1632375492476474e-18,
    1.6640288840366519e-19, 1.2326139881753718e-20, 8.804385629824085e-22,
    6.072024572292472e-23, 4.048016381528315e-24, 2.6116234719537516e-25,
    1.6322646699710948e-26, 9.892513151339969e-28, 5.819125383141158e-29,
    3.325214504652090e-30, 1.847341391473383e-31, 9.985629143099369e-33,
    5.255594285841772e-34, 2.695176556841934e-35
};

// ---------------- helpers ----------------
__device__ __forceinline__ unsigned long long pk2(float lo, float hi) {
    unsigned long long u;
    asm("mov.b64 %0, {%1, %2};" : "=l"(u) : "f"(lo), "f"(hi));
    return u;
}
__device__ __forceinline__ void upk2(unsigned long long u, float& lo, float& hi) {
    asm("mov.b64 {%0, %1}, %2;" : "=f"(lo), "=f"(hi) : "l"(u));
}
#define FFMA2(acc, a, b) \
    asm("fma.rn.f32x2 %0, %1, %2, %0;" : "+l"(acc) : "l"(a), "l"(b))
#define FADD2(dst, a, b) \
    asm("add.rn.f32x2 %0, %1, %2;" : "=l"(dst) : "l"(a), "l"(b))

__device__ __forceinline__ float tanh_apx(float x) {
    float y;
    asm("tanh.approx.f32 %0, %1;" : "=f"(y) : "f"(x));
    return y;
}

// moment accumulation helper (per-thread partial for fixed k)
__device__ __forceinline__ float moment_partial(const float* __restrict__ src,
                                                int n, int k, int tid, int stride) {
    float macc = 0.f;
    for (int p = tid; p < n; p += stride) {
        float t = src[p];
        bool ok = (t > 0.f) && (t < 8.f);     // beyond 8: exp(-t^2) < e^-64
        float wp = ok ? __expf(-t * t) : 0.f;
        float base = ok ? t : 0.f;            // keep base finite -> no 0*Inf
        int kk = k;
        while (kk) { if (kk & 1) wp *= base; base *= base; kk >>= 1; }
        macc += wp;
    }
    return macc;
}

// ================= kernel 1: rollout (72 blocks x 256) =================
// Blocks 0-31: TWO batches each (warps 0-3 batch A, warps 4-7 batch B).
//   Per batch-warpgroup (4 warps): warp ww, lane l owns rows
//     r0 = gate*64 + ww*16 + us  and  r1 = r0 + 8   (gate=l>>3, us=l&7).
//   Both rows share the same 16 hx LDS.128 per step. Gate activations are
//   exchanged with 6 parallel shuffles; lanes 0-7 update 2 units each.
//   hv folded 8->4 lanes with one shuffle -> 16 slots/batch; sigma chain
//   (redundant per warp) reads all 16 with 4 LDS.128 + 7 packed FADD2.
//   The two batches interleave on the SMSPs: one batch's latency stalls are
//   filled by the other's issue. One __syncthreads per step (both batches).
// Blocks 32-71: expert moment k = blockIdx-32 on otherwise-idle SMs.
__global__ void __launch_bounds__(256, 1)
pp_rollout_kernel(const float* __restrict__ pool,
                  const float* __restrict__ Wih,
                  const float* __restrict__ Whh,
                  const float* __restrict__ bih,
                  const float* __restrict__ bhh,
                  const float* __restrict__ Vw,
                  const float* __restrict__ Vb,
                  const float* __restrict__ et) {
    const int bk   = blockIdx.x;
    const int tid  = threadIdx.x;
    const int w    = tid >> 5;
    const int l    = tid & 31;

    // ---------- expert moment blocks ----------
    if (bk >= NBLK_ROLL) {
        const int k = bk - NBLK_ROLL;     // 0..39
        float macc = moment_partial(et, NPTS, k, tid, 256);
        __shared__ float msum[8];
#pragma unroll
        for (int o = 16; o > 0; o >>= 1) macc += __shfl_xor_sync(0xffffffffu, macc, o);
        if (l == 0) msum[w] = macc;
        __syncthreads();
        if (tid == 0) {
            double s = (double)((msum[0] + msum[1]) + (msum[2] + msum[3]))
                     + (double)((msum[4] + msum[5]) + (msum[6] + msum[7]));
            g_Me[k] = s;
        }
        return;
    }

    // ---------- rollout blocks ----------
    const int half = w >> 2;              // 0 = batch A, 1 = batch B
    const int b    = bk * 2 + half;
    const int ww   = w & 3;               // warp within batch-group
    const int gate = l >> 3;              // 0=i 1=f 2=g 3=o
    const int us   = l & 7;
    const int r0   = gate * 64 + ww * 16 + us;
    const int r1   = r0 + 8;

    __shared__ __align__(16) float hx_sb[2][2][HIDDEN];   // [parity][half][unit]
    __shared__ __align__(16) float hv_sb[2][2][16];
    __shared__ __align__(16) float lg_s[2][SEQ_LEN];
    __shared__ __align__(16) float cum_hist[2][SEQ_LEN];

    // preload both W_hh rows as packed f32x2 (128 regs)
    unsigned long long w2a[32], w2b[32];
    {
        const float4* wr0 = (const float4*)(Whh + r0 * HIDDEN);
        const float4* wr1 = (const float4*)(Whh + r1 * HIDDEN);
#pragma unroll
        for (int q = 0; q < 16; q++) {
            float4 v0 = wr0[q];
            w2a[2 * q]     = pk2(v0.x, v0.y);
            w2a[2 * q + 1] = pk2(v0.z, v0.w);
            float4 v1 = wr1[q];
            w2b[2 * q]     = pk2(v1.x, v1.y);
            w2b[2 * q + 1] = pk2(v1.z, v1.w);
        }
    }
    const float wih0  = Wih[r0],            wih1  = Wih[r1];
    const float bias0 = bih[r0] + bhh[r0],  bias1 = bih[r1] + bhh[r1];
    const float vb    = Vb[0];
    const bool  isg   = (gate == 2);
    const float vw0   = (l < 8) ? Vw[ww * 16 + l] : 0.f;
    const float vw1   = (l < 8) ? Vw[ww * 16 + l + 8] : 0.f;

    if (tid < 128) hx_sb[0][tid >> 6][tid & 63] = 0.f;
    if (tid < 32)  hv_sb[0][tid >> 4][tid & 15] = 0.f;
    lg_s[tid >> 7][tid & 127] =
        -__logf(pool[(bk * 2 + (tid >> 7)) * SEQ_LEN + (tid & 127)]);

    float cx0 = 0.f, cx1 = 0.f;   // lanes 0..7: cells of units ww*16+l, +8
    float cum_v = 0.f;            // redundant in every lane
    __syncthreads();

    for (int s = 0; s < SEQ_LEN; s++) {
        const int p = s & 1;

        // ---- cum/sigma chain (redundant per warp; parallel to matvec) ----
        const ulonglong2* hv4 = (const ulonglong2*)hv_sb[p][half];
        ulonglong2 va = hv4[0], vb2 = hv4[1], vc = hv4[2], vd = hv4[3];
        unsigned long long t1, t2, t3, t4, u1, u2, u3;
        FADD2(t1, va.x, va.y);
        FADD2(t2, vb2.x, vb2.y);
        FADD2(t3, vc.x, vc.y);
        FADD2(t4, vd.x, vd.y);
        FADD2(u1, t1, t2);
        FADD2(u2, t3, t4);
        FADD2(u3, u1, u2);
        float slo, shi;
        upk2(u3, slo, shi);
        float S = slo + shi;
        float z = S + vb;
        float sigma = (z > 0.f ? z : (__expf(z) - 1.f)) + 1.f;   // elu + 1
        cum_v += __fdividef(lg_s[half][s], sigma);

        // ---- matvec: both rows share the hx loads ----
        unsigned long long a0 = pk2(bias0, 0.f), a1 = 0ull, a2 = 0ull, a3 = 0ull;
        unsigned long long b0 = pk2(bias1, 0.f), b1 = 0ull, b2 = 0ull, b3 = 0ull;
        const ulonglong2* h4 = (const ulonglong2*)hx_sb[p][half];
#pragma unroll
        for (int j = 0; j < 8; j++) {
            ulonglong2 ha = h4[2 * j];
            ulonglong2 hb = h4[2 * j + 1];
            FFMA2(a0, w2a[4 * j + 0], ha.x);
            FFMA2(a1, w2a[4 * j + 1], ha.y);
            FFMA2(a2, w2a[4 * j + 2], hb.x);
            FFMA2(a3, w2a[4 * j + 3], hb.y);
            FFMA2(b0, w2b[4 * j + 0], ha.x);
            FFMA2(b1, w2b[4 * j + 1], ha.y);
            FFMA2(b2, w2b[4 * j + 2], hb.x);
            FFMA2(b3, w2b[4 * j + 3], hb.y);
        }
        unsigned long long pa0, pa1, paz, pb0, pb1, pbz;
        FADD2(pa0, a0, a1);
        FADD2(pa1, a2, a3);
        FADD2(paz, pa0, pa1);
        FADD2(pb0, b0, b1);
        FADD2(pb1, b2, b3);
        FADD2(pbz, pb0, pb1);
        float la, ha_, lb, hb_;
        upk2(paz, la, ha_);
        upk2(pbz, lb, hb_);
        float gv0 = fmaf(cum_v, wih0, la + ha_);
        float gv1 = fmaf(cum_v, wih1, lb + hb_);

        // ---- activations ----
        float pre0 = isg ? gv0 : 0.5f * gv0;
        float pre1 = isg ? gv1 : 0.5f * gv1;
        float tv0 = tanh_apx(pre0);
        float tv1 = tanh_apx(pre1);
        float act0 = isg ? tv0 : fmaf(tv0, 0.5f, 0.5f);
        float act1 = isg ? tv1 : fmaf(tv1, 0.5f, 0.5f);

        // ---- gather gates to unit lanes (6 parallel shuffles) ----
        float f0 = __shfl_sync(0xffffffffu, act0, us + 8);
        float g0 = __shfl_sync(0xffffffffu, act0, us + 16);
        float o0 = __shfl_sync(0xffffffffu, act0, us + 24);
        float f1 = __shfl_sync(0xffffffffu, act1, us + 8);
        float g1 = __shfl_sync(0xffffffffu, act1, us + 16);
        float o1 = __shfl_sync(0xffffffffu, act1, us + 24);

        float hv = 0.f;
        if (l < 8) {
            cx0 = fmaf(f0, cx0, act0 * g0);
            float h0 = o0 * tanh_apx(cx0);
            cx1 = fmaf(f1, cx1, act1 * g1);
            float h1 = o1 * tanh_apx(cx1);
            hx_sb[p ^ 1][half][ww * 16 + l]     = h0;
            hx_sb[p ^ 1][half][ww * 16 + l + 8] = h1;
            hv = fmaf(h0, vw0, h1 * vw1);
        }
        // fold 8 lanes -> 4 with one shuffle; lanes 0..3 store (16 slots/batch)
        hv += __shfl_xor_sync(0xffffffffu, hv, 4);
        if (l < 4) hv_sb[p ^ 1][half][ww * 4 + l] = hv;
        if ((tid & 127) == 0) cum_hist[half][s] = cum_v;
        __syncthreads();
    }

    // ---------------- epilogue: compaction of valid times ----------------
    {
        float t = cum_hist[tid >> 7][tid & 127];   // warp-aligned split
        bool valid = (t > 0.f) && (t < T_MAX_V);
        unsigned bal = __ballot_sync(0xffffffffu, valid);
        int base = 0;
        if (l == 0) base = atomicAdd(&g_nl, __popc(bal));
        base = __shfl_sync(0xffffffffu, base, 0);
        if (valid) g_lc[base + __popc(bal & ((1u << l) - 1u))] = t;
    }
}

// ================= kernel 2: reward (256 blocks x 256) =================
// All blocks: symmetric ll pair partial -> g_llp[bk] (distinct slots, no atomics).
// Blocks 0-39: learner moment k (expert moments were done in kernel 1).
__global__ void __launch_bounds__(NTHR_B, 4)
pp_reward_kernel() {
    const int T   = NBLK_B * NTHR_B;
    const int g   = blockIdx.x * NTHR_B + threadIdx.x;
    const int bk  = blockIdx.x;
    const int tid = threadIdx.x;
    const int wrp = tid >> 5, lane = tid & 31;
    const int nl  = g_nl;

    // ---- ll pair sum (j > i, symmetric) ----
    float acc = 0.f;
    if (nl > 0) {
        const int R = T / nl;
        if (g < R * nl) {
            const int i  = g % nl;
            const int r0 = g / nl;
            const float ti = g_lc[i];
            for (int j = i + 1 + r0; j < nl; j += R) {
                float d = ti - g_lc[j];
                acc += __expf(-d * d);
            }
        }
    }
    __shared__ float bsum[8];
#pragma unroll
    for (int o = 16; o > 0; o >>= 1) acc += __shfl_xor_sync(0xffffffffu, acc, o);
    if (lane == 0) bsum[wrp] = acc;
    __syncthreads();
    if (tid == 0) {
        float s = ((bsum[0] + bsum[1]) + (bsum[2] + bsum[3]))
                + ((bsum[4] + bsum[5]) + (bsum[6] + bsum[7]));
        g_llp[bk] = s;
    }

    // ---- learner moment blocks ----
    if (bk < KTERMS) {
        float macc = moment_partial(g_lc, nl, bk, tid, NTHR_B);
        __shared__ float msum[8];
#pragma unroll
        for (int o = 16; o > 0; o >>= 1) macc += __shfl_xor_sync(0xffffffffu, macc, o);
        if (lane == 0) msum[wrp] = macc;
        __syncthreads();
        if (tid == 0) {
            double s = (double)((msum[0] + msum[1]) + (msum[2] + msum[3]))
                     + (double)((msum[4] + msum[5]) + (msum[6] + msum[7]));
            g_Ml[bk] = s;
        }
    }
}

// ================= kernel 3: finalize (1 block x 256) =================
__global__ void __launch_bounds__(NTHR_B, 1)
pp_finalize_kernel(float* __restrict__ out) {
    const int tid = threadIdx.x;
    const int wrp = tid >> 5, lane = tid & 31;

    double d = (double)g_llp[tid];
#pragma unroll
    for (int o = 16; o > 0; o >>= 1) d += __shfl_xor_sync(0xffffffffu, d, o);
    __shared__ double wsum[8];
    if (lane == 0) wsum[wrp] = d;

    __shared__ double t_ee[KTERMS], t_le[KTERMS];
    if (tid < KTERMS) {
        double c  = c_coef[tid];
        double me = g_Me[tid];
        t_ee[tid] = c * me * me;
        t_le[tid] = c * me * g_Ml[tid];
    }
    __syncthreads();

    if (tid == 0) {
        double llp = ((wsum[0] + wsum[1]) + (wsum[2] + wsum[3]))
                   + ((wsum[4] + wsum[5]) + (wsum[6] + wsum[7]));
        double e0 = 0, e1 = 0, e2 = 0, e3 = 0, l0 = 0, l1 = 0, l2 = 0, l3 = 0;
#pragma unroll
        for (int k = 0; k < KTERMS; k += 4) {
            e0 += t_ee[k]; e1 += t_ee[k + 1]; e2 += t_ee[k + 2]; e3 += t_ee[k + 3];
            l0 += t_le[k]; l1 += t_le[k + 1]; l2 += t_le[k + 2]; l3 += t_le[k + 3];
        }
        double ee = (e0 + e1) + (e2 + e3);
        double le = (l0 + l1) + (l2 + l3);
        double ll = 2.0 * llp + (double)g_nl;   // off-diag*2 + diagonal
        out[0] = (float)(ee + ll - 2.0 * le);
        g_nl = 0;                                // reset for next replay
    }
}

// ---------------- launch ----------------
extern "C" void kernel_launch(void* const* d_in, const int* in_sizes, int n_in,
                              void* d_out, int out_size) {
    const float* pool = (const float*)d_in[0];
    const float* et   = (const float*)d_in[1];
    const float* Wih  = (const float*)d_in[2];
    const float* Whh  = (const float*)d_in[3];
    const float* bih  = (const float*)d_in[4];
    const float* bhh  = (const float*)d_in[5];
    const float* Vw   = (const float*)d_in[6];
    const float* Vb   = (const float*)d_in[7];
    float* out = (float*)d_out;

    pp_rollout_kernel<<<NBLK_ROLL + KTERMS, 256>>>(pool, Wih, Whh, bih, bhh, Vw, Vb, et);
    pp_reward_kernel<<<NBLK_B, NTHR_B>>>();
    pp_finalize_kernel<<<1, NTHR_B>>>(out);
}

// round 14
// speedup vs baseline: 1.0925x; 1.0925x over previous
#include <cuda_runtime.h>
#include <cuda_bf16.h>

#define HIDDEN   64
#define SEQ_LEN  128
#define BATCH    64
#define NPTS     (BATCH * SEQ_LEN)   // 8192
#define T_MAX_V  20.0f
#define KTERMS   40
#define NBLK_B   256                 // reward grid
#define NTHR_B   256

// ---------------- device scratch ----------------
__device__ float  g_lc[NPTS];
__device__ int    g_nl = 0;          // reset by finalize each run (graph-safe)
__device__ float  g_llp[NBLK_B];
__device__ double g_Me[KTERMS];
__device__ double g_Ml[KTERMS];

// c_k = 2^k / k!
__constant__ double c_coef[KTERMS] = {
    1.0, 2.0, 2.0, 1.3333333333333333, 0.6666666666666666,
    0.26666666666666666, 0.08888888888888889, 0.025396825396825397,
    0.006349206349206349, 0.0014109347442680775, 2.821869488536155e-04,
    5.130671797338464e-05, 8.551119662230773e-06, 1.3155568711124266e-06,
    1.8793669587320378e-07, 2.505822611642717e-08, 3.132278264553396e-09,
    3.6850332524157603e-10, 4.0944813915730673e-11, 4.3099804121822816e-12,
    4.3099804121822815e-13, 4.104743249697411e-14, 3.7315847724521917e-15,
    3.244856323871471e-16, 2.7040469365595593e-17, 2.1632375492476474e-18,
    1.6640288840366519e-19, 1.2326139881753718e-20, 8.804385629824085e-22,
    6.072024572292472e-23, 4.048016381528315e-24, 2.6116234719537516e-25,
    1.6322646699710948e-26, 9.892513151339969e-28, 5.819125383141158e-29,
    3.325214504652090e-30, 1.847341391473383e-31, 9.985629143099369e-33,
    5.255594285841772e-34, 2.695176556841934e-35
};

// ---------------- helpers ----------------
__device__ __forceinline__ unsigned long long pk2(float lo, float hi) {
    unsigned long long u;
    asm("mov.b64 %0, {%1, %2};" : "=l"(u) : "f"(lo), "f"(hi));
    return u;
}
__device__ __forceinline__ void upk2(unsigned long long u, float& lo, float& hi) {
    asm("mov.b64 {%0, %1}, %2;" : "=f"(lo), "=f"(hi) : "l"(u));
}
#define FFMA2(acc, a, b) \
    asm("fma.rn.f32x2 %0, %1, %2, %0;" : "+l"(acc) : "l"(a), "l"(b))
#define FADD2(dst, a, b) \
    asm("add.rn.f32x2 %0, %1, %2;" : "=l"(dst) : "l"(a), "l"(b))

__device__ __forceinline__ float tanh_apx(float x) {
    float y;
    asm("tanh.approx.f32 %0, %1;" : "=f"(y) : "f"(x));
    return y;
}

// moment accumulation helper (per-thread partial for fixed k)
__device__ __forceinline__ float moment_partial(const float* __restrict__ src,
                                                int n, int k, int tid, int stride) {
    float macc = 0.f;
    for (int p = tid; p < n; p += stride) {
        float t = src[p];
        bool ok = (t > 0.f) && (t < 8.f);     // beyond 8: exp(-t^2) < e^-64
        float wp = ok ? __expf(-t * t) : 0.f;
        float base = ok ? t : 0.f;            // keep base finite -> no 0*Inf
        int kk = k;
        while (kk) { if (kk & 1) wp *= base; base *= base; kk >>= 1; }
        macc += wp;
    }
    return macc;
}

// ================= kernel 1: rollout (104 blocks x 256) =================
// Blocks 0-63: LSTM rollout, one batch each.
//   Warp w, lane l owns matvec row gate*64 + w*8 + u (gate=l>>3, u=l&7).
//   KEY CHANGE vs R12: S = hx . Vw is computed PER LANE from the same 16
//   hx LDS.128 the matvec uses (Vw packed in 32 f32x2 regs). The entire
//   hv shuffle/store/load/reduction-tree path is deleted -> ~80 cycles off
//   the per-step critical chain; cross-warp traffic is hx only.
//   One __syncthreads per step; hx double-buffered on parity.
// Blocks 64-103: expert moment k = blockIdx-64 on otherwise-idle SMs.
__global__ void __launch_bounds__(256, 1)
pp_rollout_kernel(const float* __restrict__ pool,
                  const float* __restrict__ Wih,
                  const float* __restrict__ Whh,
                  const float* __restrict__ bih,
                  const float* __restrict__ bhh,
                  const float* __restrict__ Vw,
                  const float* __restrict__ Vb,
                  const float* __restrict__ et) {
    const int bk   = blockIdx.x;
    const int tid  = threadIdx.x;
    const int w    = tid >> 5;
    const int l    = tid & 31;

    // ---------- expert moment blocks ----------
    if (bk >= BATCH) {
        const int k = bk - BATCH;     // 0..39
        float macc = moment_partial(et, NPTS, k, tid, 256);
        __shared__ float msum[8];
#pragma unroll
        for (int o = 16; o > 0; o >>= 1) macc += __shfl_xor_sync(0xffffffffu, macc, o);
        if (l == 0) msum[w] = macc;
        __syncthreads();
        if (tid == 0) {
            double s = (double)((msum[0] + msum[1]) + (msum[2] + msum[3]))
                     + (double)((msum[4] + msum[5]) + (msum[6] + msum[7]));
            g_Me[k] = s;
        }
        return;
    }

    // ---------- rollout blocks ----------
    const int b    = bk;
    const int gate = l >> 3;          // 0=i 1=f 2=g 3=o
    const int ug   = l & 7;           // unit within warp's group
    const int row  = gate * 64 + w * 8 + ug;

    __shared__ __align__(16) float hx_sb[2][HIDDEN];
    __shared__ __align__(16) float lg_s[SEQ_LEN];
    __shared__ __align__(16) float cum_hist[SEQ_LEN];

    // preload W_hh row + Vw as packed f32x2 (96 weight regs)
    unsigned long long w2[32], vw2[32];
    {
        const float4* wrow = (const float4*)(Whh + row * HIDDEN);
        const float4* vrow = (const float4*)Vw;
#pragma unroll
        for (int q = 0; q < 16; q++) {
            float4 v = wrow[q];
            w2[2 * q]     = pk2(v.x, v.y);
            w2[2 * q + 1] = pk2(v.z, v.w);
            float4 u = vrow[q];
            vw2[2 * q]     = pk2(u.x, u.y);
            vw2[2 * q + 1] = pk2(u.z, u.w);
        }
    }
    const float wih  = Wih[row];
    const float bias = bih[row] + bhh[row];
    const float vb   = Vb[0];
    const bool  isg  = (gate == 2);

    if (tid < HIDDEN) hx_sb[0][tid] = 0.f;
    if (tid < SEQ_LEN) lg_s[tid] = -__logf(pool[b * SEQ_LEN + tid]);

    float cx = 0.f;       // lanes 0..7: cell state of unit w*8+l
    float cum_v = 0.f;    // redundant in every lane of every warp
    __syncthreads();

    for (int s = 0; s < SEQ_LEN; s++) {
        const int p = s & 1;

        // ---- fused matvec + S-dot over the SAME hx loads ----
        unsigned long long a0 = pk2(bias, 0.f), a1 = 0ull, a2 = 0ull, a3 = 0ull;
        unsigned long long v0 = 0ull, v1 = 0ull, v2 = 0ull, v3 = 0ull;
        const ulonglong2* h4 = (const ulonglong2*)hx_sb[p];
#pragma unroll
        for (int j = 0; j < 8; j++) {
            ulonglong2 ha = h4[2 * j];
            ulonglong2 hb = h4[2 * j + 1];
            FFMA2(a0, w2[4 * j + 0], ha.x);
            FFMA2(a1, w2[4 * j + 1], ha.y);
            FFMA2(a2, w2[4 * j + 2], hb.x);
            FFMA2(a3, w2[4 * j + 3], hb.y);
            FFMA2(v0, vw2[4 * j + 0], ha.x);
            FFMA2(v1, vw2[4 * j + 1], ha.y);
            FFMA2(v2, vw2[4 * j + 2], hb.x);
            FFMA2(v3, vw2[4 * j + 3], hb.y);
        }
        // S tree (sigma path — keep short)
        unsigned long long q0, q1, qz;
        FADD2(q0, v0, v1);
        FADD2(q1, v2, v3);
        FADD2(qz, q0, q1);
        float sl, sh;
        upk2(qz, sl, sh);
        float S = sl + sh;
        float z = S + vb;
        float sigma = (z > 0.f ? z : (__expf(z) - 1.f)) + 1.f;   // elu + 1
        cum_v += __fdividef(lg_s[s], sigma);

        // matvec tree
        unsigned long long pa0, pa1, paz;
        FADD2(pa0, a0, a1);
        FADD2(pa1, a2, a3);
        FADD2(paz, pa0, pa1);
        float la, ha_;
        upk2(paz, la, ha_);
        float gv = fmaf(cum_v, wih, la + ha_);

        // ---- activation (sigmoid via tanh identity; g-gate plain tanh) ----
        float pre = isg ? gv : 0.5f * gv;
        float tv  = tanh_apx(pre);
        float act = isg ? tv : fmaf(tv, 0.5f, 0.5f);

        // ---- gather gates to unit lanes (3 parallel shuffles) ----
        float fv = __shfl_sync(0xffffffffu, act, ug + 8);
        float gg = __shfl_sync(0xffffffffu, act, ug + 16);
        float ov = __shfl_sync(0xffffffffu, act, ug + 24);

        if (l < 8) {
            cx = fmaf(fv, cx, act * gg);
            float h = ov * tanh_apx(cx);
            hx_sb[p ^ 1][w * 8 + l] = h;
        }
        if (tid == 0) cum_hist[s] = cum_v;
        __syncthreads();
    }

    // ---------------- epilogue: compaction of valid times ----------------
    if (tid < SEQ_LEN) {
        float t = cum_hist[tid];
        bool valid = (t > 0.f) && (t < T_MAX_V);
        unsigned bal = __ballot_sync(0xffffffffu, valid);
        int base = 0;
        if (l == 0) base = atomicAdd(&g_nl, __popc(bal));
        base = __shfl_sync(0xffffffffu, base, 0);
        if (valid) g_lc[base + __popc(bal & ((1u << l) - 1u))] = t;
    }
}

// ================= kernel 2: reward (256 blocks x 256) =================
// All blocks: symmetric ll pair partial -> g_llp[bk] (distinct slots, no atomics).
// Blocks 0-39: learner moment k (expert moments were done in kernel 1).
__global__ void __launch_bounds__(NTHR_B, 4)
pp_reward_kernel() {
    const int T   = NBLK_B * NTHR_B;
    const int g   = blockIdx.x * NTHR_B + threadIdx.x;
    const int bk  = blockIdx.x;
    const int tid = threadIdx.x;
    const int wrp = tid >> 5, lane = tid & 31;
    const int nl  = g_nl;

    // ---- ll pair sum (j > i, symmetric) ----
    float acc = 0.f;
    if (nl > 0) {
        const int R = T / nl;
        if (g < R * nl) {
            const int i  = g % nl;
            const int r0 = g / nl;
            const float ti = g_lc[i];
            for (int j = i + 1 + r0; j < nl; j += R) {
                float d = ti - g_lc[j];
                acc += __expf(-d * d);
            }
        }
    }
    __shared__ float bsum[8];
#pragma unroll
    for (int o = 16; o > 0; o >>= 1) acc += __shfl_xor_sync(0xffffffffu, acc, o);
    if (lane == 0) bsum[wrp] = acc;
    __syncthreads();
    if (tid == 0) {
        float s = ((bsum[0] + bsum[1]) + (bsum[2] + bsum[3]))
                + ((bsum[4] + bsum[5]) + (bsum[6] + bsum[7]));
        g_llp[bk] = s;
    }

    // ---- learner moment blocks ----
    if (bk < KTERMS) {
        float macc = moment_partial(g_lc, nl, bk, tid, NTHR_B);
        __shared__ float msum[8];
#pragma unroll
        for (int o = 16; o > 0; o >>= 1) macc += __shfl_xor_sync(0xffffffffu, macc, o);
        if (lane == 0) msum[wrp] = macc;
        __syncthreads();
        if (tid == 0) {
            double s = (double)((msum[0] + msum[1]) + (msum[2] + msum[3]))
                     + (double)((msum[4] + msum[5]) + (msum[6] + msum[7]));
            g_Ml[bk] = s;
        }
    }
}

// ================= kernel 3: finalize (1 block x 256) =================
__global__ void __launch_bounds__(NTHR_B, 1)
pp_finalize_kernel(float* __restrict__ out) {
    const int tid = threadIdx.x;
    const int wrp = tid >> 5, lane = tid & 31;

    double d = (double)g_llp[tid];
#pragma unroll
    for (int o = 16; o > 0; o >>= 1) d += __shfl_xor_sync(0xffffffffu, d, o);
    __shared__ double wsum[8];
    if (lane == 0) wsum[wrp] = d;

    __shared__ double t_ee[KTERMS], t_le[KTERMS];
    if (tid < KTERMS) {
        double c  = c_coef[tid];
        double me = g_Me[tid];
        t_ee[tid] = c * me * me;
        t_le[tid] = c * me * g_Ml[tid];
    }
    __syncthreads();

    if (tid == 0) {
        double llp = ((wsum[0] + wsum[1]) + (wsum[2] + wsum[3]))
                   + ((wsum[4] + wsum[5]) + (wsum[6] + wsum[7]));
        double e0 = 0, e1 = 0, e2 = 0, e3 = 0, l0 = 0, l1 = 0, l2 = 0, l3 = 0;
#pragma unroll
        for (int k = 0; k < KTERMS; k += 4) {
            e0 += t_ee[k]; e1 += t_ee[k + 1]; e2 += t_ee[k + 2]; e3 += t_ee[k + 3];
            l0 += t_le[k]; l1 += t_le[k + 1]; l2 += t_le[k + 2]; l3 += t_le[k + 3];
        }
        double ee = (e0 + e1) + (e2 + e3);
        double le = (l0 + l1) + (l2 + l3);
        double ll = 2.0 * llp + (double)g_nl;   // off-diag*2 + diagonal
        out[0] = (float)(ee + ll - 2.0 * le);
        g_nl = 0;                                // reset for next replay
    }
}

// ---------------- launch ----------------
extern "C" void kernel_launch(void* const* d_in, const int* in_sizes, int n_in,
                              void* d_out, int out_size) {
    const float* pool = (const float*)d_in[0];
    const float* et   = (const float*)d_in[1];
    const float* Wih  = (const float*)d_in[2];
    const float* Whh  = (const float*)d_in[3];
    const float* bih  = (const float*)d_in[4];
    const float* bhh  = (const float*)d_in[5];
    const float* Vw   = (const float*)d_in[6];
    const float* Vb   = (const float*)d_in[7];
    float* out = (float*)d_out;

    pp_rollout_kernel<<<BATCH + KTERMS, 256>>>(pool, Wih, Whh, bih, bhh, Vw, Vb, et);
    pp_reward_kernel<<<NBLK_B, NTHR_B>>>();
    pp_finalize_kernel<<<1, NTHR_B>>>(out);
}